// round 5
// baseline (speedup 1.0000x reference)
#include <cuda_runtime.h>
#include <cuda_bf16.h>

#define NELEM   16384
#define THREADS 256
#define IPT     8                    // i's per thread (register blocked)
#define TI      (THREADS * IPT)      // 2048 i per block
#define TJ      256                  // j tile per block (single shared tile)
#define GRIDX   (NELEM / TI)         // 8
#define GRIDY   (NELEM / TJ)         // 64
#define NBLOCKS (GRIDX * GRIDY)      // 512

// Per-block partials; overwritten with '=' each launch (deterministic across
// graph replays, no init kernel needed).
__device__ float g_bsum[NBLOCKS];
__device__ int   g_hist[NELEM];

__global__ void zero_hist_kernel() {
    g_hist[blockIdx.x * blockDim.x + threadIdx.x] = 0;
}

__global__ void hist_kernel(const int* __restrict__ ranks) {
    const int i = blockIdx.x * blockDim.x + threadIdx.x;
    // ranks are in [0, NELEM) by construction; mask is a safety net so a bad
    // value produces a wrong answer (detectable) instead of a memory fault.
    atomicAdd(&g_hist[ranks[i] & (NELEM - 1)], 1);
}

__global__ __launch_bounds__(THREADS)
void pair_tile_kernel(const float* __restrict__ scores,
                      const int* __restrict__ ranks) {
    __shared__ float2 tile[TJ];
    __shared__ float  red_s[THREADS / 32];

    const int tid   = threadIdx.x;
    const int ibase = blockIdx.x * TI;
    const int jbase = blockIdx.y * TJ;

    // Hoist per-i state: c = 1 - s_i, plus this i's rank.
    float cst[IPT];
    int   ri[IPT];
#pragma unroll
    for (int k = 0; k < IPT; ++k) {
        const int i = ibase + tid + k * THREADS;
        cst[k] = 1.0f - scores[i];
        ri[k]  = ranks[i];
    }

    {
        const int j = jbase + tid;
        tile[tid] = make_float2(scores[j], __int_as_float(ranks[j]));
    }
    __syncthreads();

    float lsum = 0.0f;
#pragma unroll 4
    for (int jj = 0; jj < TJ; ++jj) {
        const float2 v  = tile[jj];            // warp-uniform broadcast LDS.64
        const float  sj = v.x;
        const int    rj = __float_as_int(v.y);
#pragma unroll
        for (int k = 0; k < IPT; ++k) {
            const bool  p = ri[k] < rj;
            const float t = fmaxf(cst[k] + sj, 0.0f);
            lsum += p ? t : 0.0f;
        }
    }

    // Warp reduce, then cross-warp via shared.
#pragma unroll
    for (int off = 16; off; off >>= 1)
        lsum += __shfl_down_sync(0xffffffffu, lsum, off);
    if ((tid & 31) == 0) red_s[tid >> 5] = lsum;
    __syncthreads();
    if (tid == 0) {
        float bs = 0.0f;
#pragma unroll
        for (int w = 0; w < THREADS / 32; ++w) bs += red_s[w];
        g_bsum[blockIdx.y * GRIDX + blockIdx.x] = bs;
    }
}

#define RED_T 512
__global__ __launch_bounds__(RED_T)
void final_reduce_kernel(float* __restrict__ out) {
    __shared__ double    ssum[RED_T];
    __shared__ long long sc2[RED_T];
    const int tid = threadIdx.x;

    // One block partial per thread (NBLOCKS == RED_T).
    ssum[tid] = (double)g_bsum[tid];

    // Sum of squared multiplicities over this thread's hist slice.
    long long c2 = 0;
#pragma unroll
    for (int k = 0; k < NELEM / RED_T; ++k) {
        const long long c = (long long)g_hist[tid * (NELEM / RED_T) + k];
        c2 += c * c;
    }
    sc2[tid] = c2;
    __syncthreads();

#pragma unroll
    for (int off = RED_T / 2; off; off >>= 1) {
        if (tid < off) {
            ssum[tid] += ssum[tid + off];
            sc2[tid]  += sc2[tid + off];
        }
        __syncthreads();
    }
    if (tid == 0) {
        const long long total = (long long)NELEM * (long long)NELEM;
        const long long cnt   = (total - sc2[0]) / 2;   // #(r_i < r_j) ordered pairs
        out[0] = (cnt > 0) ? (float)(ssum[0] / (double)cnt) : 0.0f;
    }
}

extern "C" void kernel_launch(void* const* d_in, const int* in_sizes, int n_in,
                              void* d_out, int out_size) {
    const float* scores = (const float*)d_in[0];
    const int*   ranks  = (const int*)d_in[1];
    float*       out    = (float*)d_out;

    zero_hist_kernel<<<NELEM / 256, 256>>>();
    hist_kernel<<<NELEM / 256, 256>>>(ranks);
    pair_tile_kernel<<<dim3(GRIDX, GRIDY), THREADS>>>(scores, ranks);
    final_reduce_kernel<<<1, RED_T>>>(out);
}